// round 10
// baseline (speedup 1.0000x reference)
#include <cuda_runtime.h>
#include <cuda_fp16.h>

// ROIPooler: multi-level FPN RoIAlign (torchvision, aligned=True)
// Inputs: x2 [2,256,200,304], x3 [2,256,100,152], x4 [2,256,50,76],
//         x5 [2,256,25,38], boxes [2,256,4]   Output: [512,256,7,7] f32
//
// Phase 1 (4 launches, proven near bandwidth-bound): transpose each level to
//   channels-last fp16 scratch g_trans[(pxbase + b*HW + y*W + x)*256 + c].
// Phase 2: per (box, 128-ch) block. Per output bin, the 4 sample points' 16
//   bilinear corners are DEDUPLICATED into ~9 unique (pixel, weight) entries
//   (weights pre-summed in fp32) — ~40% fewer gather loads + FMAs. Each
//   entry is a warp-wide contiguous 8B/lane load (4 ch/lane). Outputs smem-
//   staged (16B-aligned!), flushed as contiguous float4.

#define OUTSZ 7
#define SRATE 2
#define NSAMP 14
#define NBINS 49
#define C_TOT 256
#define N_PER_B 256
#define NBOX_TOT 512

#define HW0 (200*304)   // 60800
#define HW1 (100*152)   // 15200
#define HW2 (50*76)     // 3800
#define HW3 (25*38)     // 950
#define PX0 0
#define PX1 (2*HW0)
#define PX2 (PX1 + 2*HW1)
#define PX3 (PX2 + 2*HW2)
#define TOTAL_PX (PX3 + 2*HW3)  // 161500

// 82.7 MB channels-last fp16 scratch (device global: allowed)
__device__ __align__(16) __half g_trans[(size_t)TOTAL_PX * C_TOT];

// ---------------- phase 1: [B,C,HW] f32 -> [B,HW,C] fp16 -------------------
__global__ __launch_bounds__(256)
void transpose_kernel(const float* __restrict__ in, int HW, int pxbase)
{
    __shared__ float tile[64][33];
    const int hw0 = blockIdx.x * 32;
    const int c0  = blockIdx.y * 64;
    const int b   = blockIdx.z;
    const int w    = threadIdx.x >> 5;
    const int lane = threadIdx.x & 31;

    const int hw = hw0 + lane;
    if (hw < HW) {
        #pragma unroll
        for (int i = 0; i < 8; i++) {
            const int row = w * 8 + i;
            tile[row][lane] =
                in[(size_t)(b * C_TOT + c0 + row) * HW + hw];
        }
    }
    __syncthreads();

    __half2* __restrict__ outp = (__half2*)g_trans;
    #pragma unroll
    for (int i = 0; i < 4; i++) {
        const int hwr = w * 4 + i;
        const int hww = hw0 + hwr;
        if (hww < HW) {
            const float a = tile[2 * lane    ][hwr];
            const float c = tile[2 * lane + 1][hwr];
            outp[(size_t)(pxbase + b * HW + hww) * (C_TOT / 2)
                 + (c0 >> 1) + lane] = __floats2half2_rn(a, c);
        }
    }
}

// ---------------- phase 2: gather with per-bin corner dedup ----------------
#define GTHREADS 256
#define CSPLIT 2
#define C_PER 128

__global__ __launch_bounds__(GTHREADS)
void gather_kernel(const float* __restrict__ boxes, float* __restrict__ out)
{
    __shared__ int   s_y0[NSAMP], s_y1[NSAMP], s_x0[NSAMP], s_x1[NSAMP];
    __shared__ float s_fy[NSAMP], s_fx[NSAMP], s_wy[NSAMP], s_wx[NSAMP];
    __shared__ __align__(16) int   s_cnt [NBINS + 3];   // pad keeps layout 16B-friendly
    __shared__ __align__(16) int   s_doff[NBINS][16];   // deduped pixel offsets
    __shared__ __align__(16) float s_dwt [NBINS][16];   // summed weights
    __shared__ __align__(16) float s_out[C_PER * NBINS]; // 25088 B staging

    const int n    = blockIdx.x;
    const int cs   = blockIdx.y;
    const int tid  = threadIdx.x;
    const int w    = tid >> 5;
    const int lane = tid & 31;

    // ---- box params / level select ----
    const float bx1 = __ldg(boxes + n * 4 + 0);
    const float by1 = __ldg(boxes + n * 4 + 1);
    const float bx2 = __ldg(boxes + n * 4 + 2);
    const float by2 = __ldg(boxes + n * 4 + 3);

    const float size = sqrtf((bx2 - bx1) * (by2 - by1));
    float lf = floorf(4.0f + log2f(size / 224.0f + 1e-8f));
    lf = fminf(fmaxf(lf, 2.0f), 5.0f);
    const int lvl = (int)lf - 2;
    const int b = n / N_PER_B;

    int H, W, HW, pxb;
    float scale;
    switch (lvl) {
        case 0:  H = 200; W = 304; HW = HW0; pxb = PX0; scale = 0.25f;    break;
        case 1:  H = 100; W = 152; HW = HW1; pxb = PX1; scale = 0.125f;   break;
        case 2:  H = 50;  W = 76;  HW = HW2; pxb = PX2; scale = 0.0625f;  break;
        default: H = 25;  W = 38;  HW = HW3; pxb = PX3; scale = 0.03125f; break;
    }
    const int pxbase = pxb + b * HW;

    const float X1 = bx1 * scale - 0.5f;
    const float Y1 = by1 * scale - 0.5f;
    const float bin_w = (bx2 - bx1) * scale / (float)OUTSZ;
    const float bin_h = (by2 - by1) * scale / (float)OUTSZ;

    // ---- stage 1: per-axis tables ----
    if (tid < NSAMP) {
        const int p = tid >> 1;
        const int s = tid & 1;
        const float g = (float)p + ((float)s + 0.5f) / (float)SRATE;
        {
            const float yc = Y1 + g * bin_h;
            const bool valid = (yc >= -1.0f) && (yc <= (float)H);
            float c = fminf(fmaxf(yc, 0.0f), (float)(H - 1));
            const float c0 = floorf(c);
            const int i0 = (int)c0;
            s_y0[tid] = i0;
            s_y1[tid] = min(i0 + 1, H - 1);
            s_fy[tid] = c - c0;
            s_wy[tid] = valid ? 1.0f : 0.0f;
        }
        {
            const float xc = X1 + g * bin_w;
            const bool valid = (xc >= -1.0f) && (xc <= (float)W);
            float c = fminf(fmaxf(xc, 0.0f), (float)(W - 1));
            const float c0 = floorf(c);
            const int i0 = (int)c0;
            s_x0[tid] = i0;
            s_x1[tid] = min(i0 + 1, W - 1);
            s_fx[tid] = c - c0;
            s_wx[tid] = valid ? 1.0f : 0.0f;
        }
    }
    __syncthreads();

    // ---- stage 2: per-bin dedup of 16 corners -> <=16 unique entries ----
    if (tid < NBINS) {
        const int ph = tid / OUTSZ;
        const int pw = tid - ph * OUTSZ;
        int   cnt = 0;
        int   offs[16];
        float wts [16];
        #pragma unroll
        for (int sy = 0; sy < SRATE; sy++) {
            const int iy = 2 * ph + sy;
            const float vy = s_wy[iy];
            const float fy = s_fy[iy], ofy = 1.0f - fy;
            const int r0 = s_y0[iy] * W, r1 = s_y1[iy] * W;
            #pragma unroll
            for (int sx = 0; sx < SRATE; sx++) {
                const int ix = 2 * pw + sx;
                const float v  = vy * s_wx[ix] * 0.25f;
                const float fx = s_fx[ix], ofx = 1.0f - fx;
                const int c0 = s_x0[ix], c1 = s_x1[ix];
                const int   co[4] = { r0 + c0, r0 + c1, r1 + c0, r1 + c1 };
                const float cw[4] = { v * ofy * ofx, v * ofy * fx,
                                      v * fy  * ofx, v * fy  * fx };
                #pragma unroll
                for (int k = 0; k < 4; k++) {
                    bool found = false;
                    for (int m = 0; m < cnt; m++) {
                        if (offs[m] == co[k]) { wts[m] += cw[k]; found = true; break; }
                    }
                    if (!found) { offs[cnt] = co[k]; wts[cnt] = cw[k]; cnt++; }
                }
            }
        }
        s_cnt[tid] = cnt;
        for (int m = 0; m < cnt; m++) {
            s_doff[tid][m] = offs[m];
            s_dwt [tid][m] = wts [m];
        }
    }
    __syncthreads();

    // ---- stage 3: channels-last gather over deduped entries ----
    const __half2* __restrict__ base =
        (const __half2*)g_trans + (size_t)pxbase * (C_TOT / 2) + cs * (C_PER / 2);

    for (int r = w; r < NBINS; r += 8) {
        const int cnt = s_cnt[r];
        float a0 = 0.f, a1 = 0.f, a2 = 0.f, a3 = 0.f;
        for (int m = 0; m < cnt; m++) {
            const int   off = s_doff[r][m];
            const float wt  = s_dwt [r][m];
            const uint2 raw =
                ((const uint2*)(base + (size_t)off * (C_TOT / 2)))[lane];
            const float2 f0 = __half22float2(*(const __half2*)&raw.x);
            const float2 f1 = __half22float2(*(const __half2*)&raw.y);
            a0 = fmaf(f0.x, wt, a0);
            a1 = fmaf(f0.y, wt, a1);
            a2 = fmaf(f1.x, wt, a2);
            a3 = fmaf(f1.y, wt, a3);
        }
        const int cl = lane * 4;
        s_out[(cl + 0) * NBINS + r] = a0;
        s_out[(cl + 1) * NBINS + r] = a1;
        s_out[(cl + 2) * NBINS + r] = a2;
        s_out[(cl + 3) * NBINS + r] = a3;
    }
    __syncthreads();

    // ---- flush: out slice for (box, cs) is linear 128*49 floats ----
    float4* __restrict__ oc =
        (float4*)(out + (size_t)n * (C_TOT * NBINS) + (size_t)cs * (C_PER * NBINS));
    const float4* __restrict__ so = (const float4*)s_out;
    for (int i = tid; i < (C_PER * NBINS) / 4; i += GTHREADS)
        oc[i] = so[i];
}

extern "C" void kernel_launch(void* const* d_in, const int* in_sizes, int n_in,
                              void* d_out, int out_size)
{
    const float* x2    = (const float*)d_in[0];
    const float* x3    = (const float*)d_in[1];
    const float* x4    = (const float*)d_in[2];
    const float* x5    = (const float*)d_in[3];
    const float* boxes = (const float*)d_in[4];
    float* out = (float*)d_out;

    transpose_kernel<<<dim3((HW0 + 31) / 32, 4, 2), 256>>>(x2, HW0, PX0);
    transpose_kernel<<<dim3((HW1 + 31) / 32, 4, 2), 256>>>(x3, HW1, PX1);
    transpose_kernel<<<dim3((HW2 + 31) / 32, 4, 2), 256>>>(x4, HW2, PX2);
    transpose_kernel<<<dim3((HW3 + 31) / 32, 4, 2), 256>>>(x5, HW3, PX3);

    gather_kernel<<<dim3(NBOX_TOT, CSPLIT), GTHREADS>>>(boxes, out);
}

// round 12
// speedup vs baseline: 1.2542x; 1.2542x over previous
#include <cuda_runtime.h>
#include <cuda_fp16.h>

// ROIPooler: multi-level FPN RoIAlign (torchvision, aligned=True)
// Inputs: x2 [2,256,200,304], x3 [2,256,100,152], x4 [2,256,50,76],
//         x5 [2,256,25,38], boxes [2,256,4]   Output: [512,256,7,7] f32
//
// Phase 1 (4 launches, proven near bandwidth-bound): transpose each level to
//   channels-last fp16 scratch g_trans[(pxbase + b*HW + y*W + x)*256 + c].
// Phase 2: per (box, 128-ch) block. Statically-unrolled 16-corner bilinear
//   gather per bin, TWO bins per warp iteration (32 LDGs in flight). Each
//   corner is a warp-wide contiguous 8B/lane load (4 ch/lane). Staging and
//   flush identical to the proven R8 kernel ([c*49+r] scalar stores,
//   16B-aligned float4 linear flush).

#define OUTSZ 7
#define SRATE 2
#define NSAMP 14
#define NPTS  196
#define NBINS 49
#define C_TOT 256
#define N_PER_B 256
#define NBOX_TOT 512

#define HW0 (200*304)   // 60800
#define HW1 (100*152)   // 15200
#define HW2 (50*76)     // 3800
#define HW3 (25*38)     // 950
#define PX0 0
#define PX1 (2*HW0)
#define PX2 (PX1 + 2*HW1)
#define PX3 (PX2 + 2*HW2)
#define TOTAL_PX (PX3 + 2*HW3)  // 161500

// 82.7 MB channels-last fp16 scratch (device global: allowed)
__device__ __align__(16) __half g_trans[(size_t)TOTAL_PX * C_TOT];

// ---------------- phase 1: [B,C,HW] f32 -> [B,HW,C] fp16 -------------------
__global__ __launch_bounds__(256)
void transpose_kernel(const float* __restrict__ in, int HW, int pxbase)
{
    __shared__ float tile[64][33];
    const int hw0 = blockIdx.x * 32;
    const int c0  = blockIdx.y * 64;
    const int b   = blockIdx.z;
    const int w    = threadIdx.x >> 5;
    const int lane = threadIdx.x & 31;

    const int hw = hw0 + lane;
    if (hw < HW) {
        #pragma unroll
        for (int i = 0; i < 8; i++) {
            const int row = w * 8 + i;
            tile[row][lane] =
                in[(size_t)(b * C_TOT + c0 + row) * HW + hw];
        }
    }
    __syncthreads();

    __half2* __restrict__ outp = (__half2*)g_trans;
    #pragma unroll
    for (int i = 0; i < 4; i++) {
        const int hwr = w * 4 + i;
        const int hww = hw0 + hwr;
        if (hww < HW) {
            const float a = tile[2 * lane    ][hwr];
            const float c = tile[2 * lane + 1][hwr];
            outp[(size_t)(pxbase + b * HW + hww) * (C_TOT / 2)
                 + (c0 >> 1) + lane] = __floats2half2_rn(a, c);
        }
    }
}

// ---------------- phase 2: gather (2 bins/warp-iter) -----------------------
#define GTHREADS 256
#define CSPLIT 2
#define C_PER 128

__global__ __launch_bounds__(GTHREADS)
void gather_kernel(const float* __restrict__ boxes, float* __restrict__ out)
{
    __shared__ int   s_y0[NSAMP], s_y1[NSAMP], s_x0[NSAMP], s_x1[NSAMP];
    __shared__ float s_fy[NSAMP], s_fx[NSAMP], s_wy[NSAMP], s_wx[NSAMP];
    __shared__ __align__(16) int4   s_o4[NPTS];
    __shared__ __align__(16) float4 s_w4[NPTS];
    __shared__ __align__(16) float  s_out[C_PER * NBINS];   // 25088 B staging

    const int n    = blockIdx.x;
    const int cs   = blockIdx.y;
    const int tid  = threadIdx.x;
    const int w    = tid >> 5;
    const int lane = tid & 31;

    // ---- box params / level select ----
    const float bx1 = __ldg(boxes + n * 4 + 0);
    const float by1 = __ldg(boxes + n * 4 + 1);
    const float bx2 = __ldg(boxes + n * 4 + 2);
    const float by2 = __ldg(boxes + n * 4 + 3);

    const float size = sqrtf((bx2 - bx1) * (by2 - by1));
    float lf = floorf(4.0f + log2f(size / 224.0f + 1e-8f));
    lf = fminf(fmaxf(lf, 2.0f), 5.0f);
    const int lvl = (int)lf - 2;
    const int b = n / N_PER_B;

    int H, W, HW, pxb;
    float scale;
    switch (lvl) {
        case 0:  H = 200; W = 304; HW = HW0; pxb = PX0; scale = 0.25f;    break;
        case 1:  H = 100; W = 152; HW = HW1; pxb = PX1; scale = 0.125f;   break;
        case 2:  H = 50;  W = 76;  HW = HW2; pxb = PX2; scale = 0.0625f;  break;
        default: H = 25;  W = 38;  HW = HW3; pxb = PX3; scale = 0.03125f; break;
    }
    const int pxbase = pxb + b * HW;

    const float X1 = bx1 * scale - 0.5f;
    const float Y1 = by1 * scale - 0.5f;
    const float bin_w = (bx2 - bx1) * scale / (float)OUTSZ;
    const float bin_h = (by2 - by1) * scale / (float)OUTSZ;

    // ---- stage 1: per-axis tables ----
    if (tid < NSAMP) {
        const int p = tid >> 1;
        const int s = tid & 1;
        const float g = (float)p + ((float)s + 0.5f) / (float)SRATE;
        {
            const float yc = Y1 + g * bin_h;
            const bool valid = (yc >= -1.0f) && (yc <= (float)H);
            float c = fminf(fmaxf(yc, 0.0f), (float)(H - 1));
            const float c0 = floorf(c);
            const int i0 = (int)c0;
            s_y0[tid] = i0;
            s_y1[tid] = min(i0 + 1, H - 1);
            s_fy[tid] = c - c0;
            s_wy[tid] = valid ? 1.0f : 0.0f;
        }
        {
            const float xc = X1 + g * bin_w;
            const bool valid = (xc >= -1.0f) && (xc <= (float)W);
            float c = fminf(fmaxf(xc, 0.0f), (float)(W - 1));
            const float c0 = floorf(c);
            const int i0 = (int)c0;
            s_x0[tid] = i0;
            s_x1[tid] = min(i0 + 1, W - 1);
            s_fx[tid] = c - c0;
            s_wx[tid] = valid ? 1.0f : 0.0f;
        }
    }
    __syncthreads();

    // ---- stage 2: per-sample-point corner offsets + weights ----
    for (int pt = tid; pt < NPTS; pt += GTHREADS) {
        const int iy = pt / NSAMP;
        const int ix = pt - iy * NSAMP;
        const float v   = s_wy[iy] * s_wx[ix] * 0.25f;
        const float fy  = s_fy[iy], ofy = 1.0f - fy;
        const float fx  = s_fx[ix], ofx = 1.0f - fx;
        const int r0 = s_y0[iy] * W;
        const int r1 = s_y1[iy] * W;
        const int c0 = s_x0[ix];
        const int c1 = s_x1[ix];
        s_o4[pt] = make_int4(r0 + c0, r0 + c1, r1 + c0, r1 + c1);
        s_w4[pt] = make_float4(v * ofy * ofx, v * ofy * fx,
                               v * fy  * ofx, v * fy  * fx);
    }
    __syncthreads();

    // ---- stage 3: channels-last gather, TWO bins per warp iteration ----
    const __half2* __restrict__ base =
        (const __half2*)g_trans + (size_t)pxbase * (C_TOT / 2) + cs * (C_PER / 2);

    for (int rA = w; rA < NBINS; rA += 16) {
        const int  rB   = rA + 8;
        const bool has2 = (rB < NBINS);

        const int phA = rA / OUTSZ, pwA = rA - phA * OUTSZ;
        const int ptA = (2 * phA) * NSAMP + 2 * pwA;
        // bin B (fall back to bin A's points with zero weights if absent)
        const int rBs = has2 ? rB : rA;
        const int phB = rBs / OUTSZ, pwB = rBs - phB * OUTSZ;
        const int ptB = (2 * phB) * NSAMP + 2 * pwB;
        const float mB = has2 ? 1.0f : 0.0f;

        float A0 = 0.f, A1 = 0.f, A2 = 0.f, A3 = 0.f;
        float B0 = 0.f, B1 = 0.f, B2 = 0.f, B3 = 0.f;

        #pragma unroll
        for (int sy = 0; sy < SRATE; sy++) {
            #pragma unroll
            for (int sx = 0; sx < SRATE; sx++) {
                const int dpt = sy * NSAMP + sx;
                const int4   oA = s_o4[ptA + dpt];
                const float4 wA = s_w4[ptA + dpt];
                const int4   oB = s_o4[ptB + dpt];
                float4 wB = s_w4[ptB + dpt];
                wB.x *= mB; wB.y *= mB; wB.z *= mB; wB.w *= mB;

                #define CORNER(OFF, WT, P, Q, R, S)                            \
                {                                                              \
                    const uint2 raw =                                          \
                        ((const uint2*)(base + (size_t)(OFF) * (C_TOT / 2)))[lane]; \
                    const float2 f0 = __half22float2(*(const __half2*)&raw.x); \
                    const float2 f1 = __half22float2(*(const __half2*)&raw.y); \
                    P = fmaf(f0.x, (WT), P);                                   \
                    Q = fmaf(f0.y, (WT), Q);                                   \
                    R = fmaf(f1.x, (WT), R);                                   \
                    S = fmaf(f1.y, (WT), S);                                   \
                }
                CORNER(oA.x, wA.x, A0, A1, A2, A3)
                CORNER(oA.y, wA.y, A0, A1, A2, A3)
                CORNER(oA.z, wA.z, A0, A1, A2, A3)
                CORNER(oA.w, wA.w, A0, A1, A2, A3)
                CORNER(oB.x, wB.x, B0, B1, B2, B3)
                CORNER(oB.y, wB.y, B0, B1, B2, B3)
                CORNER(oB.z, wB.z, B0, B1, B2, B3)
                CORNER(oB.w, wB.w, B0, B1, B2, B3)
                #undef CORNER
            }
        }

        // staging identical to proven R8 layout: [c*49 + r] scalar stores
        const int cl = lane * 4;
        s_out[(cl + 0) * NBINS + rA] = A0;
        s_out[(cl + 1) * NBINS + rA] = A1;
        s_out[(cl + 2) * NBINS + rA] = A2;
        s_out[(cl + 3) * NBINS + rA] = A3;
        if (has2) {
            s_out[(cl + 0) * NBINS + rB] = B0;
            s_out[(cl + 1) * NBINS + rB] = B1;
            s_out[(cl + 2) * NBINS + rB] = B2;
            s_out[(cl + 3) * NBINS + rB] = B3;
        }
    }
    __syncthreads();

    // ---- flush: out slice for (box, cs) is linear 128*49 floats ----
    float4* __restrict__ oc =
        (float4*)(out + (size_t)n * (C_TOT * NBINS) + (size_t)cs * (C_PER * NBINS));
    const float4* __restrict__ so = (const float4*)s_out;
    for (int i = tid; i < (C_PER * NBINS) / 4; i += GTHREADS)
        oc[i] = so[i];
}

extern "C" void kernel_launch(void* const* d_in, const int* in_sizes, int n_in,
                              void* d_out, int out_size)
{
    const float* x2    = (const float*)d_in[0];
    const float* x3    = (const float*)d_in[1];
    const float* x4    = (const float*)d_in[2];
    const float* x5    = (const float*)d_in[3];
    const float* boxes = (const float*)d_in[4];
    float* out = (float*)d_out;

    transpose_kernel<<<dim3((HW0 + 31) / 32, 4, 2), 256>>>(x2, HW0, PX0);
    transpose_kernel<<<dim3((HW1 + 31) / 32, 4, 2), 256>>>(x3, HW1, PX1);
    transpose_kernel<<<dim3((HW2 + 31) / 32, 4, 2), 256>>>(x4, HW2, PX2);
    transpose_kernel<<<dim3((HW3 + 31) / 32, 4, 2), 256>>>(x5, HW3, PX3);

    gather_kernel<<<dim3(NBOX_TOT, CSPLIT), GTHREADS>>>(boxes, out);
}